// round 10
// baseline (speedup 1.0000x reference)
#include <cuda_runtime.h>
#include <cuda_bf16.h>
#include <stdint.h>

// HashEmbedder (instant-NGP style multiresolution hash grid)
// x:      [N,3] float32  (d_in[0])
// tables: [16, 2^19, 2] float32  (d_in[1])
// out:    [N, 32] float32 (level-major per point)
//
// One thread per (point, level). x-prime == 1, so for even bx the two
// x-corners of a (j,k) pair are adjacent table entries -> one LDG.128.
// This round: force occupancy back up (launch_bounds minBlocks=6) and
// shorten live ranges so regalloc fits 42 regs.

#define NL 16
#define LOG2_T 19
#define TSIZE (1u << LOG2_T)
#define TMASK (TSIZE - 1u)
#define PR1 2654435761u
#define PR2 805459861u

#define TPB 256
#define PPB (TPB / NL)    // 16 points per block

// floor(16 * 2^(l/3))
__device__ __constant__ float c_res[NL] = {
    16.f, 20.f, 25.f, 32.f, 40.f, 50.f, 64.f, 80.f,
    101.f, 128.f, 161.f, 203.f, 256.f, 322.f, 406.f, 512.f
};

__device__ __forceinline__ float2 lerp2(float2 a, float2 b, float w) {
    float omw = 1.0f - w;
    float2 r;
    r.x = a.x * omw + b.x * w;
    r.y = a.y * omw + b.y * w;
    return r;
}

__global__ __launch_bounds__(TPB, 6)
void hashgrid_kernel(const float* __restrict__ x,
                     const float* __restrict__ tables,
                     float* __restrict__ out,
                     int n)
{
    __shared__ float sc[PPB * 3];   // staged coords for the block's 16 points
    __shared__ float sres[NL];      // per-level resolution (smem broadcast)

    const int tid  = threadIdx.x;
    const int base = blockIdx.x * PPB;

    if (tid < NL) sres[tid] = c_res[tid];
    if (tid < PPB * 3) {
        const long gidx = (long)base * 3 + tid;
        sc[tid] = (gidx < (long)n * 3) ? x[gidx] : 0.0f;
    }
    __syncthreads();

    const int pl = tid >> 4;        // local point index  (0..15)
    const int l  = tid & (NL - 1);  // level index        (0..15)
    const int p  = base + pl;
    if (p >= n) return;

    const float px = sc[pl * 3 + 0];
    const float py = sc[pl * 3 + 1];
    const float pz = sc[pl * 3 + 2];

    // clamp for voxel index; weights use the UNclamped coords (matches ref)
    const float cx = fminf(fmaxf(px, -1.0f), 1.0f);
    const float cy = fminf(fmaxf(py, -1.0f), 1.0f);
    const float cz = fminf(fmaxf(pz, -1.0f), 1.0f);

    const float res  = sres[l];
    const float grid = 2.0f / res;       // single true division
    const float rinv = res * 0.5f;       // 1/grid

    const float fx = floorf((cx + 1.0f) * rinv);
    const float fy = floorf((cy + 1.0f) * rinv);
    const float fz = floorf((cz + 1.0f) * rinv);

    // vmin = bl*grid + BOX_MIN ; w = (x - vmin)/grid, with unclamped x
    const float wx = (px - (fx * grid + (-1.0f))) * rinv;
    const float wy = (py - (fy * grid + (-1.0f))) * rinv;
    const float wz = (pz - (fz * grid + (-1.0f))) * rinv;

    const uint32_t bx = (uint32_t)(int)fx;
    const uint32_t by = (uint32_t)(int)fy;
    const uint32_t bz = (uint32_t)(int)fz;

    const uint32_t hy0 = by * PR1;
    const uint32_t hy1 = hy0 + PR1;
    const uint32_t hz0 = bz * PR2;
    const uint32_t hz1 = hz0 + PR2;

    // 4 (j,k) combos; corner x0 index i = (bx ^ hjk) & TMASK
    const uint32_t hjk0 = hy0 ^ hz0;
    const uint32_t hjk1 = hy0 ^ hz1;
    const uint32_t hjk2 = hy1 ^ hz0;
    const uint32_t hjk3 = hy1 ^ hz1;

    const float2* __restrict__ tab2 =
        reinterpret_cast<const float2*>(tables) + ((size_t)l << LOG2_T);
    const float4* __restrict__ tab4 =
        reinterpret_cast<const float4*>(tables) + ((size_t)l << (LOG2_T - 1));

    const uint32_t i0 = (bx ^ hjk0) & TMASK;
    const uint32_t i1 = (bx ^ hjk1) & TMASK;
    const uint32_t i2 = (bx ^ hjk2) & TMASK;
    const uint32_t i3 = (bx ^ hjk3) & TMASK;

    // ---- issue all loads first (MLP up to 8) ----
    const float4 Q0 = __ldg(&tab4[i0 >> 1]);
    const float4 Q1 = __ldg(&tab4[i1 >> 1]);
    const float4 Q2 = __ldg(&tab4[i2 >> 1]);
    const float4 Q3 = __ldg(&tab4[i3 >> 1]);

    const bool odd = (bx & 1u) != 0u;
    float2 X0 = make_float2(0.f, 0.f), X1 = X0, X2 = X0, X3 = X0;
    if (odd) {
        const uint32_t b1 = bx + 1u;
        X0 = __ldg(&tab2[(b1 ^ hjk0) & TMASK]);
        X1 = __ldg(&tab2[(b1 ^ hjk1) & TMASK]);
        X2 = __ldg(&tab2[(b1 ^ hjk2) & TMASK]);
        X3 = __ldg(&tab2[(b1 ^ hjk3) & TMASK]);
    }

    // ---- collapse x immediately per (j,k): short live ranges ----
    float2 a00, a01, a10, a11;
    {
        const float2 lo = make_float2(Q0.x, Q0.y), hi = make_float2(Q0.z, Q0.w);
        const bool s = (i0 & 1u);
        const float2 e0 = s ? hi : lo;
        const float2 e1 = odd ? X0 : (s ? lo : hi);
        a00 = lerp2(e0, e1, wx);
    }
    {
        const float2 lo = make_float2(Q1.x, Q1.y), hi = make_float2(Q1.z, Q1.w);
        const bool s = (i1 & 1u);
        const float2 e0 = s ? hi : lo;
        const float2 e1 = odd ? X1 : (s ? lo : hi);
        a01 = lerp2(e0, e1, wx);
    }
    {
        const float2 lo = make_float2(Q2.x, Q2.y), hi = make_float2(Q2.z, Q2.w);
        const bool s = (i2 & 1u);
        const float2 e0 = s ? hi : lo;
        const float2 e1 = odd ? X2 : (s ? lo : hi);
        a10 = lerp2(e0, e1, wx);
    }
    {
        const float2 lo = make_float2(Q3.x, Q3.y), hi = make_float2(Q3.z, Q3.w);
        const bool s = (i3 & 1u);
        const float2 e0 = s ? hi : lo;
        const float2 e1 = odd ? X3 : (s ? lo : hi);
        a11 = lerp2(e0, e1, wx);
    }

    const float2 b0 = lerp2(a00, a10, wy);
    const float2 b1 = lerp2(a01, a11, wy);
    const float2 r  = lerp2(b0, b1, wz);

    // coalesced: warp covers 2 points x 16 levels -> 256B contiguous
    float2* __restrict__ o = reinterpret_cast<float2*>(out) + ((size_t)p << 4) + l;
    *o = r;
}

extern "C" void kernel_launch(void* const* d_in, const int* in_sizes, int n_in,
                              void* d_out, int out_size) {
    const float* x      = (const float*)d_in[0];
    const float* tables = (const float*)d_in[1];
    float* out          = (float*)d_out;

    const int n = in_sizes[0] / 3;
    const int blocks = (n + PPB - 1) / PPB;
    hashgrid_kernel<<<blocks, TPB>>>(x, tables, out, n);
}